// round 9
// baseline (speedup 1.0000x reference)
#include <cuda_runtime.h>

// out = M rho M^T on the Hamming-weight-2 basis (N = C(32,2) = 496).
// M block-diagonal over 36 pair-blocks; TWO distinct 4x4 tile matrices
// (V_row: params 0-5, V_col: params 6-11), pyramid order {0,1,0,2,1,0}.
//   cross block (t1<t2): dim 16, B = V_t1 (x) V_t2
//   diag  block (t):     dim 6,  B = Lambda^2(V_t) (inline)
// Grid = 36 CTAs (one block-ROW each) x 512 threads:
//   load 16x496 slab coalesced (LDG.128), LEFT per-column in registers,
//   RIGHT as 36*DI (m,J) tasks on smem, store coalesced (STG.128).

#define NP  496
#define STR 500   // slab row stride (floats): 2000B, 16B-aligned

__device__ __forceinline__ int pair_idx(int a, int b) {
    return a * 31 - (a * (a - 1)) / 2 + (b - a - 1);
}

__device__ __forceinline__ void decode_block(int B, int& t1, int& t2, int& dim) {
    if (B < 28) {
        int rem = B, a = 0;
        while (rem >= 7 - a) { rem -= 7 - a; a++; }
        t1 = a; t2 = a + 1 + rem; dim = 16;
    } else {
        t1 = B - 28; t2 = t1; dim = 6;
    }
}

// P1 = {0,0,0,1,1,2}, P2 = {1,2,3,2,3,3}, 3 bits/entry
#define P1W 0x11200
#define P2W 0x1B4D1
__device__ __forceinline__ int p1of(int m) { return (P1W >> (3 * m)) & 7; }
__device__ __forceinline__ int p2of(int m) { return (P2W >> (3 * m)) & 7; }

template <int D>
__device__ __forceinline__ int gidx(int t1, int t2, int m) {
    if (D == 16) return pair_idx(4 * t1 + (m >> 2), 4 * t2 + (m & 3));
    return pair_idx(4 * t1 + p1of(m), 4 * t1 + p2of(m));
}

__device__ __forceinline__ float went(const float* U, int m, int n) {
    int a = p1of(m), b = p2of(m), g = p1of(n), d = p2of(n);
    return U[a * 4 + g] * U[b * 4 + d] - U[a * 4 + d] * U[b * 4 + g];
}

// Warp-parallel compose (warps 0 and 1): lane l<16 ends with V[l>>2][l&3].
__device__ __forceinline__ void compose_V(int tid, const float* __restrict__ thetas,
                                          float (*sV)[16]) {
    const int w = tid >> 5, lane = tid & 31;
    float s, c;
    sincosf(__ldg(thetas + w * 6 + (lane % 6)), &s, &c);
    const int r = lane >> 2;
    float v = ((lane < 16) && ((lane >> 2) == (lane & 3))) ? 1.f : 0.f;
    const int jseq[6] = {0, 1, 0, 2, 1, 0};
    #pragma unroll
    for (int gi = 0; gi < 6; gi++) {
        const int j = jseq[gi];
        float cg = __shfl_sync(0xFFFFFFFFu, c, gi);
        float sg = __shfl_sync(0xFFFFFFFFu, s, gi);
        float vu = __shfl_sync(0xFFFFFFFFu, v, (lane + 4) & 31);
        float vd = __shfl_sync(0xFFFFFFFFu, v, (lane - 4) & 31);
        if (r == j)          v = cg * v + sg * vu;
        else if (r == j + 1) v = cg * v - sg * vd;
    }
    if (lane < 16) sV[w][lane] = v;
}

template <int DI>
__device__ __forceinline__ void process_rowblock(
    const float* __restrict__ rho, float* __restrict__ out,
    const float* __restrict__ thetas,
    int T1, int T2, int tid,
    float (*sV)[16], float* slab)
{
    // ---- compose V (warps 0,1) + coalesced slab load (all threads) ---------
    if (tid < 64) compose_V(tid, thetas, sV);

    const int NQ = 124 * DI;                   // float4 count
    #pragma unroll 1
    for (int e = tid; e < NQ; e += 512) {
        int row = e / 124, q = e % 124;
        int gr = gidx<DI>(T1, T2, row);
        float4 v = __ldg(reinterpret_cast<const float4*>(rho + gr * NP + 4 * q));
        *reinterpret_cast<float4*>(&slab[row * STR + 4 * q]) = v;
    }
    __syncthreads();

    // ---- LEFT: per column, z = B_I * x in registers -------------------------
    if (tid < NP) {
        const int c = tid;
        if (DI == 16) {
            const float* V1 = sV[T1 >> 2];
            const float* V2 = sV[T2 >> 2];
            float x[16];
            #pragma unroll
            for (int m = 0; m < 16; m++) x[m] = slab[m * STR + c];
            float tmp[16];
            #pragma unroll
            for (int al = 0; al < 4; al++)
                #pragma unroll
                for (int bp = 0; bp < 4; bp++) {
                    float acc = 0.f;
                    #pragma unroll
                    for (int ap = 0; ap < 4; ap++)
                        acc += V1[al * 4 + ap] * x[ap * 4 + bp];
                    tmp[al * 4 + bp] = acc;
                }
            #pragma unroll
            for (int al = 0; al < 4; al++)
                #pragma unroll
                for (int be = 0; be < 4; be++) {
                    float acc = 0.f;
                    #pragma unroll
                    for (int bp = 0; bp < 4; bp++)
                        acc += V2[be * 4 + bp] * tmp[al * 4 + bp];
                    slab[(al * 4 + be) * STR + c] = acc;
                }
        } else {
            const float* U = sV[T1 >> 2];
            float x[6];
            #pragma unroll
            for (int m = 0; m < 6; m++) x[m] = slab[m * STR + c];
            #pragma unroll
            for (int m = 0; m < 6; m++) {
                float acc = 0.f;
                #pragma unroll
                for (int n = 0; n < 6; n++) acc += went(U, m, n) * x[n];
                slab[m * STR + c] = acc;
            }
        }
    }
    __syncthreads();

    // ---- RIGHT: tasks (m, J); in-place on slab rows -------------------------
    const int TT = 36 * DI;
    #pragma unroll 1
    for (int e = tid; e < TT; e += 512) {
        const int J = e / DI, m = e - J * DI;
        int t1, t2, DJ;
        decode_block(J, t1, t2, DJ);
        float* yrow = &slab[m * STR];
        if (DJ == 16) {
            const float* U1 = sV[t1 >> 2];
            const float* U2 = sV[t2 >> 2];
            int cb[4];
            #pragma unroll
            for (int g = 0; g < 4; g++) cb[g] = pair_idx(4 * t1 + g, 4 * t2);
            float y[16];
            #pragma unroll
            for (int g = 0; g < 4; g++)
                #pragma unroll
                for (int d = 0; d < 4; d++) y[g * 4 + d] = yrow[cb[g] + d];
            float tmp[16];
            #pragma unroll
            for (int ga = 0; ga < 4; ga++)
                #pragma unroll
                for (int dp = 0; dp < 4; dp++) {
                    float acc = 0.f;
                    #pragma unroll
                    for (int gp = 0; gp < 4; gp++)
                        acc += U1[ga * 4 + gp] * y[gp * 4 + dp];
                    tmp[ga * 4 + dp] = acc;
                }
            #pragma unroll
            for (int ga = 0; ga < 4; ga++)
                #pragma unroll
                for (int de = 0; de < 4; de++) {
                    float acc = 0.f;
                    #pragma unroll
                    for (int dp = 0; dp < 4; dp++)
                        acc += U2[de * 4 + dp] * tmp[ga * 4 + dp];
                    yrow[cb[ga] + de] = acc;
                }
        } else {
            const float* U = sV[t1 >> 2];
            int cj[6];
            #pragma unroll
            for (int k = 0; k < 6; k++)
                cj[k] = pair_idx(4 * t1 + p1of(k), 4 * t1 + p2of(k));
            float y[6];
            #pragma unroll
            for (int k = 0; k < 6; k++) y[k] = yrow[cj[k]];
            #pragma unroll
            for (int k = 0; k < 6; k++) {
                float acc = 0.f;
                #pragma unroll
                for (int n = 0; n < 6; n++) acc += went(U, k, n) * y[n];
                yrow[cj[k]] = acc;
            }
        }
    }
    __syncthreads();

    // ---- STORE: coalesced rows ----------------------------------------------
    #pragma unroll 1
    for (int e = tid; e < NQ; e += 512) {
        int row = e / 124, q = e % 124;
        int gr = gidx<DI>(T1, T2, row);
        *reinterpret_cast<float4*>(out + gr * NP + 4 * q) =
            *reinterpret_cast<const float4*>(&slab[row * STR + 4 * q]);
    }
}

__global__ void __launch_bounds__(512, 1)
rbs_kernel(const float* __restrict__ rho, float* __restrict__ out,
           const float* __restrict__ thetas)
{
    __shared__ __align__(16) float sV[2][16];
    __shared__ __align__(16) float slab[16 * STR];

    const int tid = threadIdx.x;
    int T1, T2, DI;
    decode_block(blockIdx.x, T1, T2, DI);

    if (DI == 16) process_rowblock<16>(rho, out, thetas, T1, T2, tid, sV, slab);
    else          process_rowblock< 6>(rho, out, thetas, T1, T2, tid, sV, slab);
}

extern "C" void kernel_launch(void* const* d_in, const int* in_sizes, int n_in,
                              void* d_out, int out_size) {
    // metadata order: rho, thetas, A_stack, B_stack, C_stack, u_idx, p_idx
    const float* rho    = (const float*)d_in[0];
    const float* thetas = (const float*)d_in[1];
    float* out = (float*)d_out;

    rbs_kernel<<<36, 512>>>(rho, out, thetas);
}

// round 10
// speedup vs baseline: 1.0295x; 1.0295x over previous
#include <cuda_runtime.h>

// out = M rho M^T on the Hamming-weight-2 basis (N = C(32,2) = 496).
// M block-diagonal over 36 pair-blocks; TWO distinct 4x4 tile matrices
// (V_row: params 0-5, V_col: params 6-11), pyramid order {0,1,0,2,1,0}.
//   cross block (t1<t2): dim 16, B = V_t1 (x) V_t2
//   diag  block (t):     dim 6,  B = Lambda^2(V_t) (inline)
// Two fully-coalesced passes:
//   pass1: Y = M rho   (row mixing; 36 block-rows x 4 col chunks = 144 CTAs)
//   pass2: out = Y M^T (column mixing, row-local; 124 CTAs x 4 rows, PDL)

#define NP 496

__device__ __align__(16) float gY[NP * NP];   // intermediate, L2-resident

__device__ __forceinline__ int pair_idx(int a, int b) {
    return a * 31 - (a * (a - 1)) / 2 + (b - a - 1);
}

__device__ __forceinline__ void decode_block(int B, int& t1, int& t2, int& dim) {
    if (B < 28) {
        int rem = B, a = 0;
        while (rem >= 7 - a) { rem -= 7 - a; a++; }
        t1 = a; t2 = a + 1 + rem; dim = 16;
    } else {
        t1 = B - 28; t2 = t1; dim = 6;
    }
}

// P1 = {0,0,0,1,1,2}, P2 = {1,2,3,2,3,3}, 3 bits/entry
#define P1W 0x11200
#define P2W 0x1B4D1
__device__ __forceinline__ int p1of(int m) { return (P1W >> (3 * m)) & 7; }
__device__ __forceinline__ int p2of(int m) { return (P2W >> (3 * m)) & 7; }

template <int D>
__device__ __forceinline__ int gidx(int t1, int t2, int m) {
    if (D == 16) return pair_idx(4 * t1 + (m >> 2), 4 * t2 + (m & 3));
    return pair_idx(4 * t1 + p1of(m), 4 * t1 + p2of(m));
}

__device__ __forceinline__ float went(const float* U, int m, int n) {
    int a = p1of(m), b = p2of(m), g = p1of(n), d = p2of(n);
    return U[a * 4 + g] * U[b * 4 + d] - U[a * 4 + d] * U[b * 4 + g];
}

// Warp-parallel compose (warps 0,1): lane l<16 ends holding V[l>>2][l&3].
__device__ __forceinline__ void compose_V(int tid, const float* __restrict__ thetas,
                                          float (*sV)[16]) {
    const int w = tid >> 5, lane = tid & 31;
    float s, c;
    sincosf(__ldg(thetas + w * 6 + (lane % 6)), &s, &c);
    const int r = lane >> 2;
    float v = ((lane < 16) && ((lane >> 2) == (lane & 3))) ? 1.f : 0.f;
    const int jseq[6] = {0, 1, 0, 2, 1, 0};
    #pragma unroll
    for (int gi = 0; gi < 6; gi++) {
        const int j = jseq[gi];
        float cg = __shfl_sync(0xFFFFFFFFu, c, gi);
        float sg = __shfl_sync(0xFFFFFFFFu, s, gi);
        float vu = __shfl_sync(0xFFFFFFFFu, v, (lane + 4) & 31);
        float vd = __shfl_sync(0xFFFFFFFFu, v, (lane - 4) & 31);
        if (r == j)          v = cg * v + sg * vu;
        else if (r == j + 1) v = cg * v - sg * vd;
    }
    if (lane < 16) sV[w][lane] = v;
}

// ---------------------------------------------------------------------------
// Pass 1: Y = M * rho. CTA = (block-row I, col chunk k): 16(6) x 124 slab.
// ---------------------------------------------------------------------------
template <int DI>
__device__ __forceinline__ void pass1_body(
    const float* __restrict__ rho, const float* __restrict__ thetas,
    int T1, int T2, int c0, int tid, float (*sV)[16], float* slab /*stride 128*/)
{
    if (tid < 64) compose_V(tid, thetas, sV);

    const int NQ = 31 * DI;
    #pragma unroll 1
    for (int e = tid; e < NQ; e += 256) {
        int row = e / 31, q = e % 31;
        int gr = gidx<DI>(T1, T2, row);
        float4 v = __ldg(reinterpret_cast<const float4*>(rho + gr * NP + c0 + 4 * q));
        *reinterpret_cast<float4*>(&slab[row * 128 + 4 * q]) = v;
    }
    __syncthreads();

    if (tid < 124) {
        const int c = tid;
        if (DI == 16) {
            const float* V1 = sV[T1 >> 2];
            const float* V2 = sV[T2 >> 2];
            float x[16];
            #pragma unroll
            for (int m = 0; m < 16; m++) x[m] = slab[m * 128 + c];
            float tmp[16];
            #pragma unroll
            for (int al = 0; al < 4; al++)
                #pragma unroll
                for (int bp = 0; bp < 4; bp++) {
                    float acc = 0.f;
                    #pragma unroll
                    for (int ap = 0; ap < 4; ap++)
                        acc += V1[al * 4 + ap] * x[ap * 4 + bp];
                    tmp[al * 4 + bp] = acc;
                }
            #pragma unroll
            for (int al = 0; al < 4; al++)
                #pragma unroll
                for (int be = 0; be < 4; be++) {
                    float acc = 0.f;
                    #pragma unroll
                    for (int bp = 0; bp < 4; bp++)
                        acc += V2[be * 4 + bp] * tmp[al * 4 + bp];
                    slab[(al * 4 + be) * 128 + c] = acc;
                }
        } else {
            const float* U = sV[T1 >> 2];
            float x[6];
            #pragma unroll
            for (int m = 0; m < 6; m++) x[m] = slab[m * 128 + c];
            #pragma unroll
            for (int m = 0; m < 6; m++) {
                float acc = 0.f;
                #pragma unroll
                for (int n = 0; n < 6; n++) acc += went(U, m, n) * x[n];
                slab[m * 128 + c] = acc;
            }
        }
    }
    __syncthreads();

    #pragma unroll 1
    for (int e = tid; e < NQ; e += 256) {
        int row = e / 31, q = e % 31;
        int gr = gidx<DI>(T1, T2, row);
        *reinterpret_cast<float4*>(&gY[gr * NP + c0 + 4 * q]) =
            *reinterpret_cast<const float4*>(&slab[row * 128 + 4 * q]);
    }
}

__global__ void __launch_bounds__(256, 4)
rbs_pass1(const float* __restrict__ rho, const float* __restrict__ thetas)
{
    __shared__ __align__(16) float sV[2][16];
    __shared__ __align__(16) float slab[16 * 128];

    const int tid = threadIdx.x;
    const int I = blockIdx.x >> 2, c0 = (blockIdx.x & 3) * 124;
    int T1, T2, DI;
    decode_block(I, T1, T2, DI);

    if (DI == 16) pass1_body<16>(rho, thetas, T1, T2, c0, tid, sV, slab);
    else          pass1_body< 6>(rho, thetas, T1, T2, c0, tid, sV, slab);
}

// ---------------------------------------------------------------------------
// Pass 2: out = Y * M^T. CTA = 4 full rows; column mixing is row-local.
// ---------------------------------------------------------------------------
__global__ void __launch_bounds__(256, 4)
rbs_pass2(float* __restrict__ out, const float* __restrict__ thetas)
{
    __shared__ __align__(16) float sV[2][16];
    __shared__ __align__(16) float srow[4][512];

    const int tid = threadIdx.x;
    const int r0 = blockIdx.x * 4;

    if (tid < 64) compose_V(tid, thetas, sV);

    cudaGridDependencySynchronize();   // gY (pass1 output) now valid

    #pragma unroll 1
    for (int e = tid; e < 496; e += 256) {       // 4 rows x 124 float4
        int row = e / 124, q = e % 124;
        *reinterpret_cast<float4*>(&srow[row][4 * q]) =
            __ldg(reinterpret_cast<const float4*>(&gY[(r0 + row) * NP + 4 * q]));
    }
    __syncthreads();

    if (tid < 144) {                              // (row, J) tasks: 4 x 36
        const int rl = tid / 36, J = tid % 36;
        int t1, t2, DJ;
        decode_block(J, t1, t2, DJ);
        float* yrow = srow[rl];
        if (DJ == 16) {
            const float* U1 = sV[t1 >> 2];
            const float* U2 = sV[t2 >> 2];
            int cb[4];
            #pragma unroll
            for (int g = 0; g < 4; g++) cb[g] = pair_idx(4 * t1 + g, 4 * t2);
            float y[16];
            #pragma unroll
            for (int g = 0; g < 4; g++)
                #pragma unroll
                for (int d = 0; d < 4; d++) y[g * 4 + d] = yrow[cb[g] + d];
            float tmp[16];
            #pragma unroll
            for (int ga = 0; ga < 4; ga++)
                #pragma unroll
                for (int dp = 0; dp < 4; dp++) {
                    float acc = 0.f;
                    #pragma unroll
                    for (int gp = 0; gp < 4; gp++)
                        acc += U1[ga * 4 + gp] * y[gp * 4 + dp];
                    tmp[ga * 4 + dp] = acc;
                }
            #pragma unroll
            for (int ga = 0; ga < 4; ga++)
                #pragma unroll
                for (int de = 0; de < 4; de++) {
                    float acc = 0.f;
                    #pragma unroll
                    for (int dp = 0; dp < 4; dp++)
                        acc += U2[de * 4 + dp] * tmp[ga * 4 + dp];
                    yrow[cb[ga] + de] = acc;
                }
        } else {
            const float* U = sV[t1 >> 2];
            int cj[6];
            #pragma unroll
            for (int k = 0; k < 6; k++)
                cj[k] = pair_idx(4 * t1 + p1of(k), 4 * t1 + p2of(k));
            float y[6];
            #pragma unroll
            for (int k = 0; k < 6; k++) y[k] = yrow[cj[k]];
            #pragma unroll
            for (int k = 0; k < 6; k++) {
                float acc = 0.f;
                #pragma unroll
                for (int n = 0; n < 6; n++) acc += went(U, k, n) * y[n];
                yrow[cj[k]] = acc;
            }
        }
    }
    __syncthreads();

    #pragma unroll 1
    for (int e = tid; e < 496; e += 256) {
        int row = e / 124, q = e % 124;
        *reinterpret_cast<float4*>(out + (r0 + row) * NP + 4 * q) =
            *reinterpret_cast<const float4*>(&srow[row][4 * q]);
    }
}

extern "C" void kernel_launch(void* const* d_in, const int* in_sizes, int n_in,
                              void* d_out, int out_size) {
    // metadata order: rho, thetas, A_stack, B_stack, C_stack, u_idx, p_idx
    const float* rho    = (const float*)d_in[0];
    const float* thetas = (const float*)d_in[1];
    float* out = (float*)d_out;

    rbs_pass1<<<144, 256>>>(rho, thetas);

    // pass2 with programmatic dependent launch: overlaps launch setup with
    // pass1; device code gates gY reads on cudaGridDependencySynchronize.
    cudaLaunchConfig_t cfg = {};
    cfg.gridDim  = dim3(124, 1, 1);
    cfg.blockDim = dim3(256, 1, 1);
    cfg.dynamicSmemBytes = 0;
    cfg.stream = 0;
    cudaLaunchAttribute attr[1];
    attr[0].id = cudaLaunchAttributeProgrammaticStreamSerialization;
    attr[0].val.programmaticStreamSerializationAllowed = 1;
    cfg.attrs = attr;
    cfg.numAttrs = 1;
    cudaLaunchKernelEx(&cfg, rbs_pass2, out, thetas);
}

// round 11
// speedup vs baseline: 1.3413x; 1.3029x over previous
#include <cuda_runtime.h>

// out = M rho M^T on the Hamming-weight-2 basis (N = C(32,2) = 496).
// M block-diagonal over 36 pair-blocks; TWO distinct 4x4 tile matrices
// (V_row: params 0-5, V_col: params 6-11), pyramid order {0,1,0,2,1,0}.
//   cross block (t1<t2): dim 16, B = V_t1 (x) V_t2
//   diag  block (t):     dim 6,  B = Lambda^2(V_t) (inline)
// SYMMETRY: rho and out are symmetric -> compute only I <= J (666 CTAs),
// mirror out[J,I] = out[I,J]^T. With I<=J ordering, DI=6 & DJ=16 never occurs.
// Per CTA: gather first, warp-parallel compose overlapped, 1-2 barriers.

#define NP 496

__device__ __forceinline__ int pair_idx(int a, int b) {
    return a * 31 - (a * (a - 1)) / 2 + (b - a - 1);
}

__device__ __forceinline__ void decode_block(int B, int& t1, int& t2, int& dim) {
    if (B < 28) {
        int rem = B, a = 0;
        while (rem >= 7 - a) { rem -= 7 - a; a++; }
        t1 = a; t2 = a + 1 + rem; dim = 16;
    } else {
        t1 = B - 28; t2 = t1; dim = 6;
    }
}

__device__ __forceinline__ int tri_base(int I) { return (73 * I - I * I) >> 1; }

// P1 = {0,0,0,1,1,2}, P2 = {1,2,3,2,3,3}, 3 bits/entry
#define P1W 0x11200
#define P2W 0x1B4D1
__device__ __forceinline__ int p1of(int m) { return (P1W >> (3 * m)) & 7; }
__device__ __forceinline__ int p2of(int m) { return (P2W >> (3 * m)) & 7; }

template <int D>
__device__ __forceinline__ int gidx(int t1, int t2, int m) {
    if (D == 16) return pair_idx(4 * t1 + (m >> 2), 4 * t2 + (m & 3));
    return pair_idx(4 * t1 + p1of(m), 4 * t1 + p2of(m));
}

__device__ __forceinline__ float went(const float* U, int m, int n) {
    int a = p1of(m), b = p2of(m), g = p1of(n), d = p2of(n);
    return U[a * 4 + g] * U[b * 4 + d] - U[a * 4 + d] * U[b * 4 + g];
}

// Warp-parallel compose (warps 0,1): lane l<16 ends holding V[l>>2][l&3].
__device__ __forceinline__ void compose_V(int tid, const float* __restrict__ thetas,
                                          float (*sV)[16]) {
    const int w = tid >> 5, lane = tid & 31;
    float s, c;
    sincosf(__ldg(thetas + w * 6 + (lane % 6)), &s, &c);
    const int r = lane >> 2;
    float v = ((lane < 16) && ((lane >> 2) == (lane & 3))) ? 1.f : 0.f;
    const int jseq[6] = {0, 1, 0, 2, 1, 0};
    #pragma unroll
    for (int gi = 0; gi < 6; gi++) {
        const int j = jseq[gi];
        float cg = __shfl_sync(0xFFFFFFFFu, c, gi);
        float sg = __shfl_sync(0xFFFFFFFFu, s, gi);
        float vu = __shfl_sync(0xFFFFFFFFu, v, (lane + 4) & 31);
        float vd = __shfl_sync(0xFFFFFFFFu, v, (lane - 4) & 31);
        if (r == j)          v = cg * v + sg * vu;
        else if (r == j + 1) v = cg * v - sg * vd;
    }
    if (lane < 16) sV[w][lane] = v;
}

__device__ __forceinline__ float4 shflx4(float4 a, int m) {
    float4 r;
    r.x = __shfl_xor_sync(0xFFFFFFFFu, a.x, m);
    r.y = __shfl_xor_sync(0xFFFFFFFFu, a.y, m);
    r.z = __shfl_xor_sync(0xFFFFFFFFu, a.z, m);
    r.w = __shfl_xor_sync(0xFFFFFFFFu, a.w, m);
    return r;
}

__device__ __forceinline__ void accum_right(float4& o, const float4* U2r,
                                            float cf, float4 y) {
    float s0 = U2r[0].x * y.x + U2r[0].y * y.y + U2r[0].z * y.z + U2r[0].w * y.w;
    float s1 = U2r[1].x * y.x + U2r[1].y * y.y + U2r[1].z * y.z + U2r[1].w * y.w;
    float s2 = U2r[2].x * y.x + U2r[2].y * y.y + U2r[2].z * y.z + U2r[2].w * y.w;
    float s3 = U2r[3].x * y.x + U2r[3].y * y.y + U2r[3].z * y.z + U2r[3].w * y.w;
    o.x += cf * s0; o.y += cf * s1; o.z += cf * s2; o.w += cf * s3;
}

// ----- DI = DJ = 16 (cross x cross): one barrier, butterfly right stage -----
__device__ __forceinline__ void path_cross16(
    const float* __restrict__ rho, float* __restrict__ out,
    const float* __restrict__ thetas,
    int T1, int T2, int t1, int t2, int tid, bool mirror,
    float (*sV)[16], float (*bufA)[20])
{
    const int m_s = tid >> 2, g_s = tid & 3;
    const int growm = gidx<16>(T1, T2, m_s);
    const int colbase = pair_idx(4 * t1 + g_s, 4 * t2);
    const int rowoff = growm * NP;
    float4 r4;
    {
        const float* p = rho + rowoff + colbase;
        r4.x = __ldg(p); r4.y = __ldg(p + 1); r4.z = __ldg(p + 2); r4.w = __ldg(p + 3);
    }
    compose_V(tid, thetas, sV);              // overlaps the gather
    *reinterpret_cast<float4*>(&bufA[m_s][4 * g_s]) = r4;
    __syncthreads();                         // sV + bufA ready

    // LEFT fused: acc = (B_I * bufA) strip (m_s, cols 4g_s..4g_s+3)
    float4 acc = {0.f, 0.f, 0.f, 0.f};
    {
        const float4 V1r = *reinterpret_cast<const float4*>(&sV[T1 >> 2][(m_s >> 2) * 4]);
        const float4 V2r = *reinterpret_cast<const float4*>(&sV[T2 >> 2][(m_s & 3) * 4]);
        const float v1[4] = {V1r.x, V1r.y, V1r.z, V1r.w};
        const float v2[4] = {V2r.x, V2r.y, V2r.z, V2r.w};
        #pragma unroll
        for (int ap = 0; ap < 4; ap++) {
            float4 s2 = {0.f, 0.f, 0.f, 0.f};
            #pragma unroll
            for (int bp = 0; bp < 4; bp++) {
                float4 x = *reinterpret_cast<const float4*>(&bufA[ap * 4 + bp][4 * g_s]);
                s2.x += v2[bp] * x.x; s2.y += v2[bp] * x.y;
                s2.z += v2[bp] * x.z; s2.w += v2[bp] * x.w;
            }
            acc.x += v1[ap] * s2.x; acc.y += v1[ap] * s2.y;
            acc.z += v1[ap] * s2.z; acc.w += v1[ap] * s2.w;
        }
    }

    // quad butterfly: row quads gp = g_s, g_s^1, g_s^2, g_s^3
    float4 A = acc;
    float4 B = shflx4(A, 1);
    float4 C = shflx4(A, 2);
    float4 D = shflx4(B, 2);

    const float* U1 = sV[t1 >> 2];
    float4 U2r[4];
    #pragma unroll
    for (int r = 0; r < 4; r++)
        U2r[r] = *reinterpret_cast<const float4*>(&sV[t2 >> 2][r * 4]);
    float4 o = {0.f, 0.f, 0.f, 0.f};
    accum_right(o, U2r, U1[g_s * 4 + g_s],       A);
    accum_right(o, U2r, U1[g_s * 4 + (g_s ^ 1)], B);
    accum_right(o, U2r, U1[g_s * 4 + (g_s ^ 2)], C);
    accum_right(o, U2r, U1[g_s * 4 + (g_s ^ 3)], D);

    float* p = out + rowoff + colbase;
    p[0] = o.x; p[1] = o.y; p[2] = o.z; p[3] = o.w;
    if (mirror) {
        out[(colbase + 0) * NP + growm] = o.x;
        out[(colbase + 1) * NP + growm] = o.y;
        out[(colbase + 2) * NP + growm] = o.z;
        out[(colbase + 3) * NP + growm] = o.w;
    }
}

// ----- DJ = 6 (J diagonal): DI = 16 or 6, smem 3-stage, 2 barriers ----------
template <int DI>
__device__ __forceinline__ void path_jdiag(
    const float* __restrict__ rho, float* __restrict__ out,
    const float* __restrict__ thetas,
    int T1, int T2, int t1, int tid, bool mirror,
    float (*sV)[16], float (*bufA)[20], float (*bufB)[20])
{
    float rs[2];
    #pragma unroll
    for (int k = 0; k < 2; k++) {
        int e = tid + 64 * k;
        if (e < DI * 6)
            rs[k] = __ldg(rho + gidx<DI>(T1, T2, e / 6) * NP + gidx<6>(t1, t1, e % 6));
    }
    compose_V(tid, thetas, sV);
    #pragma unroll
    for (int k = 0; k < 2; k++) {
        int e = tid + 64 * k;
        if (e < DI * 6) bufA[e / 6][e % 6] = rs[k];
    }
    __syncthreads();

    #pragma unroll
    for (int k = 0; k < 2; k++) {
        int e = tid + 64 * k;
        if (e < DI * 6) {
            int m = e / 6, c = e % 6;
            float acc = 0.f;
            if (DI == 16) {
                const float4 V1r = *reinterpret_cast<const float4*>(&sV[T1 >> 2][(m >> 2) * 4]);
                const float4 V2r = *reinterpret_cast<const float4*>(&sV[T2 >> 2][(m & 3) * 4]);
                const float v1[4] = {V1r.x, V1r.y, V1r.z, V1r.w};
                const float v2[4] = {V2r.x, V2r.y, V2r.z, V2r.w};
                #pragma unroll
                for (int ap = 0; ap < 4; ap++) {
                    float s2 = 0.f;
                    #pragma unroll
                    for (int bp = 0; bp < 4; bp++)
                        s2 += v2[bp] * bufA[ap * 4 + bp][c];
                    acc += v1[ap] * s2;
                }
            } else {
                const float* U = sV[T1 >> 2];
                #pragma unroll
                for (int n = 0; n < 6; n++)
                    acc += went(U, m, n) * bufA[n][c];
            }
            bufB[m][c] = acc;
        }
    }
    __syncthreads();

    const float* UJ = sV[t1 >> 2];
    #pragma unroll
    for (int k = 0; k < 2; k++) {
        int e = tid + 64 * k;
        if (e < DI * 6) {
            int m = e / 6, c = e % 6;
            float acc = 0.f;
            #pragma unroll
            for (int n = 0; n < 6; n++)
                acc += went(UJ, c, n) * bufB[m][n];
            const int gr = gidx<DI>(T1, T2, m);
            const int gc = gidx<6>(t1, t1, c);
            out[gr * NP + gc] = acc;
            if (mirror) out[gc * NP + gr] = acc;
        }
    }
}

__global__ void __launch_bounds__(64, 16)
rbs_kernel(const float* __restrict__ rho, float* __restrict__ out,
           const float* __restrict__ thetas)
{
    __shared__ __align__(16) float sV[2][16];
    __shared__ __align__(16) float bufA[16][20];
    __shared__ __align__(16) float bufB[16][20];

    const int tid = threadIdx.x;

    // decode upper-triangular pair (I <= J) from blockIdx
    const int k = blockIdx.x;
    int I = (int)((73.0f - sqrtf(5329.0f - 8.0f * (float)k)) * 0.5f);
    while (tri_base(I + 1) <= k) ++I;
    while (tri_base(I) > k) --I;
    const int J = I + (k - tri_base(I));
    const bool mirror = (I != J);

    int T1, T2, DI, t1, t2, DJ;
    decode_block(I, T1, T2, DI);
    decode_block(J, t1, t2, DJ);

    if (DJ == 16) {
        // I <= J and J cross => I cross too
        path_cross16(rho, out, thetas, T1, T2, t1, t2, tid, mirror, sV, bufA);
    } else if (DI == 16) {
        path_jdiag<16>(rho, out, thetas, T1, T2, t1, tid, mirror, sV, bufA, bufB);
    } else {
        path_jdiag< 6>(rho, out, thetas, T1, T2, t1, tid, mirror, sV, bufA, bufB);
    }
}

extern "C" void kernel_launch(void* const* d_in, const int* in_sizes, int n_in,
                              void* d_out, int out_size) {
    // metadata order: rho, thetas, A_stack, B_stack, C_stack, u_idx, p_idx
    const float* rho    = (const float*)d_in[0];
    const float* thetas = (const float*)d_in[1];
    float* out = (float*)d_out;

    rbs_kernel<<<666, 64>>>(rho, out, thetas);
}